// round 14
// baseline (speedup 1.0000x reference)
#include <cuda_runtime.h>
#include <cstdint>
#include <cstddef>

// Repara_PhC via sparsity (R11).
// Per 128x64-px tile: warp 0 ballot-compacts the in-range holes (order
// preserved -> deterministic sums, ONE __syncthreads total), then the block
// either writes the constant sigmoid (cnt==0, bitwise-equal op sequence) or
// evaluates separable Gaussians (outer product of ex2 factors) + fused sigmoid.
// vs R9: tile doubled in i (half the preambles), list build confined to warp 0
// (1 barrier instead of 3), 8x4 microtile (0.375 ex2 per px, was 0.5).

#define GN     4001
#define NTJ    63          // j tiles: 63 x 64 = 4032 >= 4001
#define NTI    32          // i tiles: 32 x 128 = 4096 >= 4001
#define TPXJ   64
#define TPXI   128
#define MAXH   32
#define NHOLES 192
#define LOG2E  1.442695041f

__device__ __forceinline__ float ex2f(float x) {
    float r; asm("ex2.approx.ftz.f32 %0, %1;" : "=f"(r) : "f"(x)); return r;
}
__device__ __forceinline__ float rcpf(float x) {
    float r; asm("rcp.approx.ftz.f32 %0, %1;" : "=f"(r) : "f"(x)); return r;
}

__global__ __launch_bounds__(256) void eval_tiles(const float* __restrict__ holes,
                                                  const float* __restrict__ Tptr,
                                                  float* __restrict__ out) {
    const int i0 = blockIdx.y * TPXI;
    const int j0 = blockIdx.x * TPXJ;
    const int tid = threadIdx.x;

    __shared__ float hx[MAXH], hy[MAXH], hc[MAXH];
    __shared__ int scnt;

    // ---- warp 0 builds the hole list alone: 6 rounds of 32, no inter-warp sync ----
    if (tid < 32) {
        const float xlo = -10.f + 0.005f * (float)i0;
        const float xhi = xlo + 0.005f * (float)(TPXI - 1);
        const float ylo = -10.f + 0.005f * (float)j0;
        const float yhi = ylo + 0.005f * (float)(TPXJ - 1);
        int base = 0;
        #pragma unroll
        for (int s = 0; s < 6; ++s) {
            const int h = s * 32 + tid;
            const float cx = holes[3 * h];
            const float cy = holes[3 * h + 1];
            const float cs = holes[3 * h + 2];
            const float dx = fmaxf(fmaxf(xlo - cx, cx - xhi), 0.f);
            const float dy = fmaxf(fmaxf(ylo - cy, cy - yhi), 0.f);
            const bool in = (dx * dx + dy * dy) <= (2.f * cs * cs * 16.2f);  // exp >= ~1e-7
            const unsigned m = __ballot_sync(0xffffffffu, in);
            if (in) {
                int pos = base + __popc(m & ((1u << tid) - 1u));
                if (pos < MAXH) {
                    hx[pos] = cx; hy[pos] = cy;
                    hc[pos] = -LOG2E / (2.f * cs * cs);
                }
            }
            base += __popc(m);
        }
        if (tid == 0) scnt = base < MAXH ? base : MAXH;
    }
    __syncthreads();
    const int cnt = scnt;

    // thread -> 8 rows (i = i0+ty+32*ii) x 4 cols (j = j0+tx+16*jj).
    // A warp's 32 lanes = 2 rows x 16 consecutive j -> dense 64B store runs.
    const int tx = tid & 15;
    const int ty = tid >> 4;          // 0..15 ... wait: 256/16 = 16 -> rows via stride 16
    const float k = LOG2E * rcpf(*Tptr);

    // ty covers 16 base rows; ii stride 16 covers 128 rows (8 passes).
    if (cnt == 0) {
        const float v = rcpf(1.f + ex2f(0.5f * k));   // Z=0: same op sequence as below
        #pragma unroll
        for (int ii = 0; ii < 8; ++ii) {
            const int i = i0 + ty + 16 * ii;
            if (i >= GN) continue;
            const uint32_t rb = (uint32_t)i * GN;
            #pragma unroll
            for (int jj = 0; jj < 4; ++jj) {
                const int j = j0 + tx + 16 * jj;
                if (j < GN) out[rb + j] = v;
            }
        }
        return;
    }

    float xv[8], yv[4];
    #pragma unroll
    for (int ii = 0; ii < 8; ++ii) xv[ii] = -10.f + 0.005f * (float)(i0 + ty + 16 * ii);
    #pragma unroll
    for (int jj = 0; jj < 4; ++jj) yv[jj] = -10.f + 0.005f * (float)(j0 + tx + 16 * jj);

    float acc[8][4];
    #pragma unroll
    for (int ii = 0; ii < 8; ++ii)
        #pragma unroll
        for (int jj = 0; jj < 4; ++jj) acc[ii][jj] = 0.f;

    for (int h = 0; h < cnt; ++h) {
        const float hcx = hx[h], hcy = hy[h], c = hc[h];
        float ex[8], ey[4];
        #pragma unroll
        for (int ii = 0; ii < 8; ++ii) { float d = xv[ii] - hcx; ex[ii] = ex2f(d * d * c); }
        #pragma unroll
        for (int jj = 0; jj < 4; ++jj) { float d = yv[jj] - hcy; ey[jj] = ex2f(d * d * c); }
        #pragma unroll
        for (int ii = 0; ii < 8; ++ii)
            #pragma unroll
            for (int jj = 0; jj < 4; ++jj)
                acc[ii][jj] = fmaf(ex[ii], ey[jj], acc[ii][jj]);   // 2^(c(dx^2+dy^2))
    }

    // sigmoid((Z-0.5)/T) = 1/(1 + 2^((0.5-Z)*k))
    #pragma unroll
    for (int ii = 0; ii < 8; ++ii) {
        const int i = i0 + ty + 16 * ii;
        if (i >= GN) continue;
        const uint32_t rb = (uint32_t)i * GN;
        #pragma unroll
        for (int jj = 0; jj < 4; ++jj) {
            const int j = j0 + tx + 16 * jj;
            if (j < GN) {
                float e = ex2f((0.5f - acc[ii][jj]) * k);
                out[rb + j] = rcpf(1.f + e);
            }
        }
    }
}

extern "C" void kernel_launch(void* const* d_in, const int* in_sizes, int n_in,
                              void* d_out, int out_size) {
    const float* holes = (const float*)d_in[0];   // 192 x (x0, y0, sigma)
    const float* Tptr  = (const float*)d_in[1];
    float* out = (float*)d_out;                   // 4001 x 4001 fp32

    dim3 grid(NTJ, NTI);                          // 63 x 32 = 2016 blocks
    eval_tiles<<<grid, 256>>>(holes, Tptr, out);
}

// round 15
// speedup vs baseline: 1.4459x; 1.4459x over previous
#include <cuda_runtime.h>
#include <cstdint>
#include <cstddef>

// Repara_PhC via sparsity (R15 = R10 geometry + warp0-only list build).
// Per 64x64-px tile: warp 0 alone ballot-compacts the holes within cutoff
// (6 rounds of 32, hole order preserved -> deterministic sums), ONE barrier.
// cnt==0 (~75% of tiles): block-constant sigmoid (bitwise-equal op sequence).
// cnt>0: separable Gaussian outer product (ex2 factors + FMA) + fused sigmoid.
// Stores: stride-16 j mapping -> each STG.32 writes dense 64B runs.

#define GN     4001
#define NT     63          // 63 tiles of 64 px cover 4032 >= 4001
#define TPX    64
#define MAXH   32
#define NHOLES 192
#define LOG2E  1.442695041f

__device__ __forceinline__ float ex2f(float x) {
    float r; asm("ex2.approx.ftz.f32 %0, %1;" : "=f"(r) : "f"(x)); return r;
}
__device__ __forceinline__ float rcpf(float x) {
    float r; asm("rcp.approx.ftz.f32 %0, %1;" : "=f"(r) : "f"(x)); return r;
}

__global__ __launch_bounds__(256) void eval_tiles(const float* __restrict__ holes,
                                                  const float* __restrict__ Tptr,
                                                  float* __restrict__ out) {
    const int i0 = blockIdx.y * TPX;
    const int j0 = blockIdx.x * TPX;
    const int tid = threadIdx.x;

    __shared__ float hx[MAXH], hy[MAXH], hc[MAXH];
    __shared__ int scnt;

    // ---- warp 0 builds the hole list alone: 6 rounds of 32, intra-warp only ----
    if (tid < 32) {
        const float xlo = -10.f + 0.005f * (float)i0;
        const float xhi = xlo + 0.005f * (float)(TPX - 1);
        const float ylo = -10.f + 0.005f * (float)j0;
        const float yhi = ylo + 0.005f * (float)(TPX - 1);
        int base = 0;
        #pragma unroll
        for (int s = 0; s < 6; ++s) {
            const int h = s * 32 + tid;
            const float cx = holes[3 * h];
            const float cy = holes[3 * h + 1];
            const float cs = holes[3 * h + 2];
            const float dx = fmaxf(fmaxf(xlo - cx, cx - xhi), 0.f);
            const float dy = fmaxf(fmaxf(ylo - cy, cy - yhi), 0.f);
            const bool in = (dx * dx + dy * dy) <= (2.f * cs * cs * 16.2f);  // exp >= ~1e-7
            const unsigned m = __ballot_sync(0xffffffffu, in);
            if (in) {
                int pos = base + __popc(m & ((1u << tid) - 1u));
                if (pos < MAXH) {
                    hx[pos] = cx; hy[pos] = cy;
                    hc[pos] = -LOG2E / (2.f * cs * cs);
                }
            }
            base += __popc(m);
        }
        if (tid == 0) scnt = base < MAXH ? base : MAXH;
    }
    __syncthreads();
    const int cnt = scnt;

    // thread -> 4 rows (i = i0+ty+16*ii) x 4 cols (j = j0+tx+16*jj), stride-16:
    // each STG.32 warp instruction writes 16 consecutive floats per row.
    const int tx = tid & 15;
    const int ty = tid >> 4;
    const float k = LOG2E * rcpf(*Tptr);

    if (cnt == 0) {
        // Z = 0 everywhere: same op sequence as the generic path at acc=0.
        const float v = rcpf(1.f + ex2f(0.5f * k));
        #pragma unroll
        for (int ii = 0; ii < 4; ++ii) {
            const int i = i0 + ty + 16 * ii;
            if (i >= GN) continue;
            const uint32_t rb = (uint32_t)i * GN;
            #pragma unroll
            for (int jj = 0; jj < 4; ++jj) {
                const int j = j0 + tx + 16 * jj;
                if (j < GN) out[rb + j] = v;
            }
        }
        return;
    }

    float xv[4], yv[4];
    #pragma unroll
    for (int ii = 0; ii < 4; ++ii) xv[ii] = -10.f + 0.005f * (float)(i0 + ty + 16 * ii);
    #pragma unroll
    for (int jj = 0; jj < 4; ++jj) yv[jj] = -10.f + 0.005f * (float)(j0 + tx + 16 * jj);

    float acc[4][4];
    #pragma unroll
    for (int ii = 0; ii < 4; ++ii)
        #pragma unroll
        for (int jj = 0; jj < 4; ++jj) acc[ii][jj] = 0.f;

    for (int h = 0; h < cnt; ++h) {
        const float hcx = hx[h], hcy = hy[h], c = hc[h];
        float ex[4], ey[4];
        #pragma unroll
        for (int ii = 0; ii < 4; ++ii) { float d = xv[ii] - hcx; ex[ii] = ex2f(d * d * c); }
        #pragma unroll
        for (int jj = 0; jj < 4; ++jj) { float d = yv[jj] - hcy; ey[jj] = ex2f(d * d * c); }
        #pragma unroll
        for (int ii = 0; ii < 4; ++ii)
            #pragma unroll
            for (int jj = 0; jj < 4; ++jj)
                acc[ii][jj] = fmaf(ex[ii], ey[jj], acc[ii][jj]);   // 2^(c(dx^2+dy^2))
    }

    // sigmoid((Z-0.5)/T) = 1/(1 + 2^((0.5-Z)*k))
    #pragma unroll
    for (int ii = 0; ii < 4; ++ii) {
        const int i = i0 + ty + 16 * ii;
        if (i >= GN) continue;
        const uint32_t rb = (uint32_t)i * GN;
        #pragma unroll
        for (int jj = 0; jj < 4; ++jj) {
            const int j = j0 + tx + 16 * jj;
            if (j < GN) {
                float e = ex2f((0.5f - acc[ii][jj]) * k);
                out[rb + j] = rcpf(1.f + e);
            }
        }
    }
}

extern "C" void kernel_launch(void* const* d_in, const int* in_sizes, int n_in,
                              void* d_out, int out_size) {
    const float* holes = (const float*)d_in[0];   // 192 x (x0, y0, sigma)
    const float* Tptr  = (const float*)d_in[1];
    float* out = (float*)d_out;                   // 4001 x 4001 fp32

    dim3 grid(NT, NT);                            // 63 x 63 = 3969 blocks
    eval_tiles<<<grid, 256>>>(holes, Tptr, out);
}